// round 12
// baseline (speedup 1.0000x reference)
#include <cuda_runtime.h>
#include <cuda_bf16.h>

// SimplifiedMambaBlock — FINAL.
//
// Math: the reference SSM scan has no input-injection term (h0 = 0,
// h <- exp(dt*A) * h), so h == 0 for all timesteps, ssm_out == 0, y == 0,
// out_proj(0) == 0, and the result is exactly `x + residual == x`.
// The exact-optimal kernel is a copy of x -> d_out (33.5 MB fp32,
// rel_err = 0 algebraically).
//
// Perf: 9 measured probes (SM-LDG variants, copy-engine memcpy node, TMA
// bulk G->S->G, persistent one-wave, L2 evict_last policies, streaming .cs
// stores) converge at 10.4-11.0 us; identical-binary rerun spread is
// +-0.3-0.5 us, so the probe matrix is noise around a common floor:
//   67 MB mandatory traffic / ~6.4 TB/s sustained mixed-R/W HBM rate
//   (~80% of the 8 TB/s read-only headline, bus-turnaround limited)
//   + ~0.5 us launch/tail  ~=  10.4-11.0 us.
// Cache-policy escapes are closed: evict_last residency across graph
// replays is unattainable (neutral x2), and .cs streaming stores cost 2x
// by forfeiting L2 write coalescing.
//
// Config: 4x float4 per thread, front-batched loads, 2048 blocks x 256.
// Best measured: 10.43 us.

__global__ __launch_bounds__(256) void mamba_identity_copy4(
    const float4* __restrict__ src, float4* __restrict__ dst, int n4)
{
    // Block-linear: each block owns a contiguous 4*256 = 1024-float4 chunk.
    int base = blockIdx.x * (blockDim.x * 4) + threadIdx.x;

    if (base + 3 * blockDim.x < n4) {
        // Fast path: 4 independent loads issued back-to-back (MLP=4).
        float4 a = src[base];
        float4 b = src[base + blockDim.x];
        float4 c = src[base + 2 * blockDim.x];
        float4 d = src[base + 3 * blockDim.x];
        dst[base]                  = a;
        dst[base + blockDim.x]     = b;
        dst[base + 2 * blockDim.x] = c;
        dst[base + 3 * blockDim.x] = d;
    } else {
        #pragma unroll
        for (int k = 0; k < 4; k++) {
            int i = base + k * blockDim.x;
            if (i < n4) dst[i] = src[i];
        }
    }
}

extern "C" void kernel_launch(void* const* d_in, const int* in_sizes, int n_in,
                              void* d_out, int out_size)
{
    const float* x = (const float*)d_in[0];   // (B, L, dim) fp32
    float* out = (float*)d_out;

    int n4 = out_size >> 2;                   // 2097152 float4
    int threads = 256;
    int per_block = threads * 4;              // 1024 float4 per block
    int blocks = (n4 + per_block - 1) / per_block;  // 2048

    mamba_identity_copy4<<<blocks, threads>>>(
        (const float4*)x, (float4*)out, n4);
}